// round 8
// baseline (speedup 1.0000x reference)
#include <cuda_runtime.h>

#define H 512
#define W 512
#define NB 32
#define OUTW 56            // output columns per warp (lanes 0..27 x 2)
#define STRIPS 10          // 10*56 = 560 >= 512
#define YSEGS 8
#define YLEN 64
#define WARPS_TOTAL (STRIPS * NB * YSEGS)   // 2560
#define WPB 2
#define NBLOCKS (WARPS_TOTAL / WPB)         // 1280
#define RP 256             // float2 row pitch

__device__ float g_part[NBLOCKS];
__device__ int   g_cnt = 0;

// Pair-channel horizontal 9-window sums. Lane l holds columns 2l (a0), 2l+1 (a1).
#define HSUM9P(a0, a1, hE, hO) do {                          \
    float _p  = (a0) + (a1);                                 \
    float _s  = _p + __shfl_down_sync(0xffffffffu, _p, 1);   \
    float _S4 = _s + __shfl_down_sync(0xffffffffu, _s, 2);   \
    (hE) = _S4  + __shfl_down_sync(0xffffffffu, (a0), 4);    \
    (hO) = (a1) + __shfl_down_sync(0xffffffffu, _S4, 1);     \
} while (0)

// GR: need row bounds checks; GC: need column validity (cok) checks.
template<bool GR, bool GC>
__device__ __forceinline__ float warp_cc(const float2* __restrict__ baseI,
                                         const float2* __restrict__ baseT,
                                         int y0, bool cok, bool valE, bool valO) {
    const float2* qI = baseI + (ptrdiff_t)(y0 - 4) * RP;
    const float2* qT = baseT + (ptrdiff_t)(y0 - 4) * RP;
    int gy = y0 - 4;

    float ri0[9], ri1[9], rt0[9], rt1[9];
    #pragma unroll
    for (int k = 0; k < 9; k++) { ri0[k]=0.f; ri1[k]=0.f; rt0[k]=0.f; rt1[k]=0.f; }

    float VA0=0.f, VA1=0.f, VB0=0.f, VB1=0.f, VAA0=0.f, VAA1=0.f,
          VBB0=0.f, VBB1=0.f, VAB0=0.f, VAB1=0.f;
    float acc = 0.f;
    const float inv81 = 1.0f / 81.0f;

    // load row at current (qI,qT); predicate folds away in fast instantiation
    #define LOADROW(i0v, i1v, t0v, t1v, G) do {                       \
        i0v = 0.f; i1v = 0.f; t0v = 0.f; t1v = 0.f;                   \
        bool _p = true;                                               \
        if (GC) _p = cok;                                             \
        if (GR) _p = _p && ((unsigned)(G) < H);                       \
        if (_p) {                                                     \
            const float2 _I = __ldg(qI);                              \
            const float2 _T = __ldg(qT);                              \
            i0v = _I.x; i1v = _I.y;                                   \
            t0v = fmaf(_T.x, 0.5f, 0.5f);                             \
            t1v = fmaf(_T.y, 0.5f, 0.5f);                             \
        }                                                             \
        qI += RP; qT += RP;                                           \
    } while (0)

    #define EMIT() do {                                                         \
        float SAE, SAO, SBE, SBO, SAAE, SAAO, SBBE, SBBO, SABE, SABO;           \
        HSUM9P(VA0,  VA1,  SAE,  SAO);                                          \
        HSUM9P(VB0,  VB1,  SBE,  SBO);                                          \
        HSUM9P(VAA0, VAA1, SAAE, SAAO);                                         \
        HSUM9P(VBB0, VBB1, SBBE, SBBO);                                         \
        HSUM9P(VAB0, VAB1, SABE, SABO);                                         \
        {                                                                       \
            const float tA = SAE * inv81, tB = SBE * inv81;                     \
            const float cross = fmaf(-tA, SBE, SABE);                           \
            const float ivar  = fmaf(-tA, SAE, SAAE);                           \
            const float tvar  = fmaf(-tB, SBE, SBBE);                           \
            const float cc = __fdividef(cross * cross, fmaf(tvar, ivar, 1e-5f));\
            acc += valE ? cc : 0.f;                                             \
        }                                                                       \
        {                                                                       \
            const float tA = SAO * inv81, tB = SBO * inv81;                     \
            const float cross = fmaf(-tA, SBO, SABO);                           \
            const float ivar  = fmaf(-tA, SAO, SAAO);                           \
            const float tvar  = fmaf(-tB, SBO, SBBO);                           \
            const float cc = __fdividef(cross * cross, fmaf(tvar, ivar, 1e-5f));\
            acc += valO ? cc : 0.f;                                             \
        }                                                                       \
    } while (0)

    // prefetch row gy = y0-4
    float cI0, cI1, cT0, cT1;
    LOADROW(cI0, cI1, cT0, cT1, gy);

    // ---- warmup: rows y0-4 .. y0+4 (slots 0..8), add-only ----
    #pragma unroll
    for (int i = 0; i < 9; i++) {
        float nI0, nI1, nT0, nT1;
        LOADROW(nI0, nI1, nT0, nT1, gy + 1);
        VA0 += cI0;  VA1 += cI1;  VB0 += cT0;  VB1 += cT1;
        VAA0 = fmaf(cI0, cI0, VAA0);  VAA1 = fmaf(cI1, cI1, VAA1);
        VBB0 = fmaf(cT0, cT0, VBB0);  VBB1 = fmaf(cT1, cT1, VBB1);
        VAB0 = fmaf(cI0, cT0, VAB0);  VAB1 = fmaf(cI1, cT1, VAB1);
        ri0[i] = cI0; ri1[i] = cI1; rt0[i] = cT0; rt1[i] = cT1;
        cI0 = nI0; cI1 = nI1; cT0 = nT0; cT1 = nT1;
        gy++;
    }
    EMIT();   // output row y0

    // ---- steady: 63 rows; cur row is y0+5+j*9+k, old = ring[k] (row-9) ----
    #pragma unroll 1
    for (int j = 0; j < 7; j++) {
        #pragma unroll
        for (int k = 0; k < 9; k++) {
            float nI0, nI1, nT0, nT1;
            LOADROW(nI0, nI1, nT0, nT1, gy + 1);   // last one may be an unused (in-bounds or guarded) read
            const float oi0 = ri0[k], oi1 = ri1[k], ot0 = rt0[k], ot1 = rt1[k];
            VA0 += cI0 - oi0;  VA1 += cI1 - oi1;
            VB0 += cT0 - ot0;  VB1 += cT1 - ot1;
            VAA0 = fmaf(-oi0, oi0, fmaf(cI0, cI0, VAA0));
            VAA1 = fmaf(-oi1, oi1, fmaf(cI1, cI1, VAA1));
            VBB0 = fmaf(-ot0, ot0, fmaf(cT0, cT0, VBB0));
            VBB1 = fmaf(-ot1, ot1, fmaf(cT1, cT1, VBB1));
            VAB0 = fmaf(-oi0, ot0, fmaf(cI0, cT0, VAB0));
            VAB1 = fmaf(-oi1, ot1, fmaf(cI1, cT1, VAB1));
            ri0[k] = cI0; ri1[k] = cI1; rt0[k] = cT0; rt1[k] = cT1;
            cI0 = nI0; cI1 = nI1; cT0 = nT0; cT1 = nT1;
            gy++;
            EMIT();
        }
    }
    #undef LOADROW
    #undef EMIT
    return acc;
}

__global__ __launch_bounds__(64, 10) void cc_kernel(const float* __restrict__ inp,
                                                    const float* __restrict__ tgt,
                                                    float* __restrict__ out) {
    const int lane = threadIdx.x & 31;
    const int wid  = threadIdx.x >> 5;
    const int w    = blockIdx.x * WPB + wid;

    const int strip = w % STRIPS;
    const int rem   = w / STRIPS;          // 0..255
    const int b     = rem >> 3;            // 0..31
    const int y0    = (rem & 7) * YLEN;    // 0..448

    const int xs  = strip * OUTW;
    const int gx  = xs - 4 + 2 * lane;
    const bool cok = (unsigned)gx < W;

    const int ocolE = xs + 2 * lane;
    const bool valE = (lane < 28) && (ocolE     < W);
    const bool valO = (lane < 28) && (ocolE + 1 < W);

    const size_t boff = (size_t)b * (H * W) + (cok ? gx : 0);
    const float2* baseI = (const float2*)(inp + boff);
    const float2* baseT = (const float2*)(tgt + boff);

    const bool fastR = (y0 != 0) && (y0 != (YSEGS - 1) * YLEN);
    const bool fastC = (strip >= 1) && (strip <= 8);

    float acc;
    if (fastR && fastC)      acc = warp_cc<false, false>(baseI, baseT, y0, cok, valE, valO);
    else if (fastR)          acc = warp_cc<false, true >(baseI, baseT, y0, cok, valE, valO);
    else if (fastC)          acc = warp_cc<true,  false>(baseI, baseT, y0, cok, valE, valO);
    else                     acc = warp_cc<true,  true >(baseI, baseT, y0, cok, valE, valO);

    // ---- reduction: warp -> block -> global partials -> last block finishes ----
    #pragma unroll
    for (int off = 16; off > 0; off >>= 1)
        acc += __shfl_down_sync(0xffffffffu, acc, off);

    __shared__ float sred[WPB];
    __shared__ int   slast;
    if (lane == 0) sred[wid] = acc;
    __syncthreads();
    if (threadIdx.x == 0) {
        g_part[blockIdx.x] = sred[0] + sred[1];
        __threadfence();
        int old = atomicAdd(&g_cnt, 1);
        slast = (old == NBLOCKS - 1) ? 1 : 0;
    }
    __syncthreads();

    if (slast) {
        // 1280 partials = 320 float4; 64 threads -> 5 float4 each
        double d = 0.0;
        const float4* p4 = (const float4*)g_part;
        #pragma unroll
        for (int r = 0; r < 5; r++) {
            const float4 v = p4[threadIdx.x + r * 64];
            d += (double)v.x + (double)v.y + (double)v.z + (double)v.w;
        }
        #pragma unroll
        for (int off = 16; off > 0; off >>= 1)
            d += __shfl_down_sync(0xffffffffu, d, off);
        __shared__ double dred[WPB];
        if (lane == 0) dred[wid] = d;
        __syncthreads();
        if (threadIdx.x == 0) {
            out[0] = (float)(-(dred[0] + dred[1]) / 8388608.0);   // 32*512*512
            g_cnt = 0;                            // reset for next graph replay
        }
    }
}

extern "C" void kernel_launch(void* const* d_in, const int* in_sizes, int n_in,
                              void* d_out, int out_size) {
    const float* inp = (const float*)d_in[0];
    const float* tgt = (const float*)d_in[1];
    // d_in[2] is the all-ones 9x9 filter; baked into the box sums.
    float* out = (float*)d_out;
    cc_kernel<<<NBLOCKS, 64>>>(inp, tgt, out);
}

// round 9
// speedup vs baseline: 1.1474x; 1.1474x over previous
#include <cuda_runtime.h>

#define H 512
#define W 512
#define NB 32
#define OUTW 112           // output columns per warp (lanes 0..27 x 4)
#define STRIPS 5           // 5*112 = 560 >= 512
#define YSEGS 16
#define YLEN 32
#define WARPS_TOTAL (STRIPS * NB * YSEGS)   // 2560
#define WPB 2
#define NBLOCKS (WARPS_TOTAL / WPB)         // 1280
#define RPF4 128           // float4 row pitch

__device__ float g_part[NBLOCKS];
__device__ int   g_cnt = 0;

// Quad horizontal 9-window sums. Lane l holds cols xs-4+4l .. xs-1+4l (v0..v3);
// O[o] = sum of 9 cols centered at xs+4l+o. Needs lanes l+1, l+2 (valid l<=29).
#define HQUAD(v0, v1, v2, v3, O0, O1, O2, O3) do {              \
    const float _p2 = (v0) + (v1);                              \
    const float _p3 = _p2 + (v2);                               \
    const float _Q  = _p3 + (v3);                               \
    const float _s3 = _Q - (v0);                                \
    const float _s2 = (v2) + (v3);                              \
    const float _Qn1 = __shfl_down_sync(0xffffffffu, _Q, 1);    \
    const float _Qn2 = __shfl_down_sync(0xffffffffu, _Q, 2);    \
    const float _p1n = __shfl_down_sync(0xffffffffu, (v0), 2);  \
    const float _p2n = __shfl_down_sync(0xffffffffu, _p2, 2);   \
    const float _p3n = __shfl_down_sync(0xffffffffu, _p3, 2);   \
    (O0) = _Q  + _Qn1 + _p1n;                                   \
    (O1) = _s3 + _Qn1 + _p2n;                                   \
    (O2) = _s2 + _Qn1 + _p3n;                                   \
    (O3) = (v3) + _Qn1 + _Qn2;                                  \
} while (0)

__global__ __launch_bounds__(64, 8) void cc_kernel(const float* __restrict__ inp,
                                                   const float* __restrict__ tgt,
                                                   float* __restrict__ out) {
    const int lane = threadIdx.x & 31;
    const int wid  = threadIdx.x >> 5;
    const int w    = blockIdx.x * WPB + wid;

    const int strip = w % STRIPS;
    const int rem   = w / STRIPS;          // 0..511
    const int b     = rem >> 4;            // 0..31
    const int y0    = (rem & 15) << 5;     // 0..480

    const int xs   = strip * OUTW;
    const int gx   = xs - 4 + 4 * lane;    // first col of this lane's quad (4-aligned)
    const bool cok = (unsigned)gx < W;
    const bool val = (lane < 28) && (xs + 4 * lane < W);

    const size_t boff = (size_t)b * (H * W) + (cok ? gx : 0);
    const float4* __restrict__ qI = (const float4*)(inp + boff);
    const float4* __restrict__ qT = (const float4*)(tgt + boff);

    // load one row (zero outside image), rescale T to [0,1]
    #define LOADE(G, I4, T4) do {                                  \
        I4 = make_float4(0.f, 0.f, 0.f, 0.f);                      \
        T4 = make_float4(0.f, 0.f, 0.f, 0.f);                      \
        if (cok && (unsigned)(G) < H) {                            \
            I4 = __ldg(qI + (ptrdiff_t)(G) * RPF4);                \
            const float4 _t = __ldg(qT + (ptrdiff_t)(G) * RPF4);   \
            T4.x = fmaf(_t.x, 0.5f, 0.5f);                         \
            T4.y = fmaf(_t.y, 0.5f, 0.5f);                         \
            T4.z = fmaf(_t.z, 0.5f, 0.5f);                         \
            T4.w = fmaf(_t.w, 0.5f, 0.5f);                         \
        }                                                          \
    } while (0)

    float VA[4], VB[4], VAA[4], VBB[4], VAB[4];
    #pragma unroll
    for (int c = 0; c < 4; c++) { VA[c]=0.f; VB[c]=0.f; VAA[c]=0.f; VBB[c]=0.f; VAB[c]=0.f; }
    float acc = 0.f;
    const float inv81 = 1.0f / 81.0f;

    #define EMIT() do {                                                          \
        float SA[4], SB[4], SAA[4], SBB[4], SAB[4];                              \
        HQUAD(VA[0],  VA[1],  VA[2],  VA[3],  SA[0],  SA[1],  SA[2],  SA[3]);    \
        HQUAD(VB[0],  VB[1],  VB[2],  VB[3],  SB[0],  SB[1],  SB[2],  SB[3]);    \
        HQUAD(VAA[0], VAA[1], VAA[2], VAA[3], SAA[0], SAA[1], SAA[2], SAA[3]);   \
        HQUAD(VBB[0], VBB[1], VBB[2], VBB[3], SBB[0], SBB[1], SBB[2], SBB[3]);   \
        HQUAD(VAB[0], VAB[1], VAB[2], VAB[3], SAB[0], SAB[1], SAB[2], SAB[3]);   \
        float _sum = 0.f;                                                        \
        _Pragma("unroll")                                                        \
        for (int o = 0; o < 4; o++) {                                            \
            const float tA = SA[o] * inv81, tB = SB[o] * inv81;                  \
            const float cross = fmaf(-tA, SB[o], SAB[o]);                        \
            const float ivar  = fmaf(-tA, SA[o], SAA[o]);                        \
            const float tvar  = fmaf(-tB, SB[o], SBB[o]);                        \
            _sum += __fdividef(cross * cross, fmaf(tvar, ivar, 1e-5f));          \
        }                                                                        \
        acc += val ? _sum : 0.f;                                                 \
    } while (0)

    // prefetch first row (y0-4)
    float4 nI, nT;
    LOADE(y0 - 4, nI, nT);

    // ---- warmup: rows y0-4 .. y0+4, add-only ----
    #pragma unroll
    for (int i = 0; i < 9; i++) {
        const float4 cI = nI, cT = nT;
        LOADE(y0 - 3 + i, nI, nT);
        const float eI[4] = {cI.x, cI.y, cI.z, cI.w};
        const float eT[4] = {cT.x, cT.y, cT.z, cT.w};
        #pragma unroll
        for (int c = 0; c < 4; c++) {
            VA[c]  += eI[c];
            VB[c]  += eT[c];
            VAA[c]  = fmaf(eI[c], eI[c], VAA[c]);
            VBB[c]  = fmaf(eT[c], eT[c], VBB[c]);
            VAB[c]  = fmaf(eI[c], eT[c], VAB[c]);
        }
    }
    EMIT();   // output row y0

    // ---- steady: 31 rows; enter y0+5+s (prefetched), exit y0-4+s (L1 re-load) ----
    #pragma unroll 2
    for (int s = 0; s < 31; s++) {
        const float4 cI = nI, cT = nT;
        LOADE(y0 + 6 + s, nI, nT);        // prefetch next enter (guarded)
        float4 oI, oT;
        LOADE(y0 - 4 + s, oI, oT);        // exiting row, 9 back (cache hit)
        const float eI[4] = {cI.x, cI.y, cI.z, cI.w};
        const float eT[4] = {cT.x, cT.y, cT.z, cT.w};
        const float xI[4] = {oI.x, oI.y, oI.z, oI.w};
        const float xT[4] = {oT.x, oT.y, oT.z, oT.w};
        #pragma unroll
        for (int c = 0; c < 4; c++) {
            VA[c]  += eI[c] - xI[c];
            VB[c]  += eT[c] - xT[c];
            VAA[c]  = fmaf(-xI[c], xI[c], fmaf(eI[c], eI[c], VAA[c]));
            VBB[c]  = fmaf(-xT[c], xT[c], fmaf(eT[c], eT[c], VBB[c]));
            VAB[c]  = fmaf(-xI[c], xT[c], fmaf(eI[c], eT[c], VAB[c]));
        }
        EMIT();
    }
    #undef LOADE
    #undef EMIT

    // ---- reduction: warp -> block -> global partials -> last block finishes ----
    #pragma unroll
    for (int off = 16; off > 0; off >>= 1)
        acc += __shfl_down_sync(0xffffffffu, acc, off);

    __shared__ float sred[WPB];
    __shared__ int   slast;
    if (lane == 0) sred[wid] = acc;
    __syncthreads();
    if (threadIdx.x == 0) {
        g_part[blockIdx.x] = sred[0] + sred[1];
        __threadfence();
        int old = atomicAdd(&g_cnt, 1);
        slast = (old == NBLOCKS - 1) ? 1 : 0;
    }
    __syncthreads();

    if (slast) {
        // 1280 partials = 320 float4; 64 threads -> 5 float4 each
        double d = 0.0;
        const float4* p4 = (const float4*)g_part;
        #pragma unroll
        for (int r = 0; r < 5; r++) {
            const float4 v = p4[threadIdx.x + r * 64];
            d += (double)v.x + (double)v.y + (double)v.z + (double)v.w;
        }
        #pragma unroll
        for (int off = 16; off > 0; off >>= 1)
            d += __shfl_down_sync(0xffffffffu, d, off);
        __shared__ double dred[WPB];
        if (lane == 0) dred[wid] = d;
        __syncthreads();
        if (threadIdx.x == 0) {
            out[0] = (float)(-(dred[0] + dred[1]) / 8388608.0);   // 32*512*512
            g_cnt = 0;                            // reset for next graph replay
        }
    }
}

extern "C" void kernel_launch(void* const* d_in, const int* in_sizes, int n_in,
                              void* d_out, int out_size) {
    const float* inp = (const float*)d_in[0];
    const float* tgt = (const float*)d_in[1];
    // d_in[2] is the all-ones 9x9 filter; baked into the box sums.
    float* out = (float*)d_out;
    cc_kernel<<<NBLOCKS, 64>>>(inp, tgt, out);
}

// round 10
// speedup vs baseline: 1.4161x; 1.2342x over previous
#include <cuda_runtime.h>

#define H 512
#define W 512
#define NB 32
#define OUTW 56            // output columns per warp (lanes 0..27 x 2)
#define STRIPS 10          // 10*56 = 560 >= 512
#define YSEGS 16
#define YLEN 32
#define WARPS_TOTAL (STRIPS * NB * YSEGS)   // 5120
#define WPB 2
#define NBLOCKS (WARPS_TOTAL / WPB)         // 2560
#define RP 256             // float2 row pitch

__device__ float g_part[NBLOCKS];
__device__ int   g_cnt = 0;

// Pair-channel horizontal 9-window sums. Lane l holds columns 2l (a0), 2l+1 (a1).
#define HSUM9P(a0, a1, hE, hO) do {                          \
    float _p  = (a0) + (a1);                                 \
    float _s  = _p + __shfl_down_sync(0xffffffffu, _p, 1);   \
    float _S4 = _s + __shfl_down_sync(0xffffffffu, _s, 2);   \
    (hE) = _S4  + __shfl_down_sync(0xffffffffu, (a0), 4);    \
    (hO) = (a1) + __shfl_down_sync(0xffffffffu, _S4, 1);     \
} while (0)

__global__ __launch_bounds__(64, 10) void cc_kernel(const float* __restrict__ inp,
                                                    const float* __restrict__ tgt,
                                                    float* __restrict__ out) {
    const int lane = threadIdx.x & 31;
    const int wid  = threadIdx.x >> 5;
    const int w    = blockIdx.x * WPB + wid;

    const int strip = w % STRIPS;
    const int rem   = w / STRIPS;          // 0..511
    const int b     = rem >> 4;            // 0..31
    const int y0    = (rem & 15) << 5;     // 0..480

    const int xs  = strip * OUTW;
    const int gx  = xs - 4 + 2 * lane;
    const bool cok = (unsigned)gx < W;

    const int ocolE = xs + 2 * lane;
    const bool valE = (lane < 28) && (ocolE     < W);
    const bool valO = (lane < 28) && (ocolE + 1 < W);

    const size_t boff = (size_t)b * (H * W) + (cok ? gx : 0);
    const float2* __restrict__ pI2 = (const float2*)(inp + boff);
    const float2* __restrict__ pT2 = (const float2*)(tgt + boff);

    // vertical ring buffers of RAW rows: 4 values x 9 rows = 36 regs
    float ri0[9], ri1[9], rt0[9], rt1[9];
    #pragma unroll
    for (int k = 0; k < 9; k++) { ri0[k]=0.f; ri1[k]=0.f; rt0[k]=0.f; rt1[k]=0.f; }

    float VA0=0.f, VA1=0.f, VB0=0.f, VB1=0.f, VAA0=0.f, VAA1=0.f,
          VBB0=0.f, VBB1=0.f, VAB0=0.f, VAB1=0.f, acc=0.f;
    const float inv81 = 1.0f / 81.0f;

    #define LOADROW(G, I2v, T2v) do {                              \
        I2v = make_float2(0.f, 0.f);                               \
        T2v = make_float2(0.f, 0.f);                               \
        if (cok && (unsigned)(G) < H) {                            \
            I2v = __ldg(pI2 + (ptrdiff_t)(G) * RP);                \
            const float2 _t = __ldg(pT2 + (ptrdiff_t)(G) * RP);    \
            T2v.x = fmaf(_t.x, 0.5f, 0.5f);                        \
            T2v.y = fmaf(_t.y, 0.5f, 0.5f);                        \
        }                                                          \
    } while (0)

    #define EMIT() do {                                                         \
        float SAE, SAO, SBE, SBO, SAAE, SAAO, SBBE, SBBO, SABE, SABO;           \
        HSUM9P(VA0,  VA1,  SAE,  SAO);                                          \
        HSUM9P(VB0,  VB1,  SBE,  SBO);                                          \
        HSUM9P(VAA0, VAA1, SAAE, SAAO);                                         \
        HSUM9P(VBB0, VBB1, SBBE, SBBO);                                         \
        HSUM9P(VAB0, VAB1, SABE, SABO);                                         \
        {                                                                       \
            const float tA = SAE * inv81, tB = SBE * inv81;                     \
            const float cross = fmaf(-tA, SBE, SABE);                           \
            const float ivar  = fmaf(-tA, SAE, SAAE);                           \
            const float tvar  = fmaf(-tB, SBE, SBBE);                           \
            const float cc = __fdividef(cross * cross, fmaf(tvar, ivar, 1e-5f));\
            acc += valE ? cc : 0.f;                                             \
        }                                                                       \
        {                                                                       \
            const float tA = SAO * inv81, tB = SBO * inv81;                     \
            const float cross = fmaf(-tA, SBO, SABO);                           \
            const float ivar  = fmaf(-tA, SAO, SAAO);                           \
            const float tvar  = fmaf(-tB, SBO, SBBO);                           \
            const float cc = __fdividef(cross * cross, fmaf(tvar, ivar, 1e-5f));\
            acc += valO ? cc : 0.f;                                             \
        }                                                                       \
    } while (0)

    #define STEADY(kslot, G) do {                                               \
        float2 nI, nT;                                                          \
        LOADROW((G) + 1, nI, nT);     /* prefetch next enter row */             \
        const float iv0 = cI.x, iv1 = cI.y, tv0 = cT.x, tv1 = cT.y;             \
        const float oi0 = ri0[kslot], oi1 = ri1[kslot];                         \
        const float ot0 = rt0[kslot], ot1 = rt1[kslot];                         \
        VA0 += iv0 - oi0;  VA1 += iv1 - oi1;                                    \
        VB0 += tv0 - ot0;  VB1 += tv1 - ot1;                                    \
        VAA0 = fmaf(-oi0, oi0, fmaf(iv0, iv0, VAA0));                           \
        VAA1 = fmaf(-oi1, oi1, fmaf(iv1, iv1, VAA1));                           \
        VBB0 = fmaf(-ot0, ot0, fmaf(tv0, tv0, VBB0));                           \
        VBB1 = fmaf(-ot1, ot1, fmaf(tv1, tv1, VBB1));                           \
        VAB0 = fmaf(-oi0, ot0, fmaf(iv0, tv0, VAB0));                           \
        VAB1 = fmaf(-oi1, ot1, fmaf(iv1, tv1, VAB1));                           \
        ri0[kslot] = iv0; ri1[kslot] = iv1; rt0[kslot] = tv0; rt1[kslot] = tv1; \
        cI = nI; cT = nT;                                                       \
        EMIT();                                                                 \
    } while (0)

    // prefetch first row (gy = y0-4)
    float2 cI, cT;
    LOADROW(y0 - 4, cI, cT);

    // ---- warmup: rows y0-4 .. y0+4 (slots 0..8), add-only; first output at end ----
    #pragma unroll
    for (int i = 0; i < 9; i++) {
        float2 nI, nT;
        LOADROW(y0 - 3 + i, nI, nT);
        const float iv0 = cI.x, iv1 = cI.y, tv0 = cT.x, tv1 = cT.y;
        VA0 += iv0;  VA1 += iv1;  VB0 += tv0;  VB1 += tv1;
        VAA0 = fmaf(iv0, iv0, VAA0);  VAA1 = fmaf(iv1, iv1, VAA1);
        VBB0 = fmaf(tv0, tv0, VBB0);  VBB1 = fmaf(tv1, tv1, VBB1);
        VAB0 = fmaf(iv0, tv0, VAB0);  VAB1 = fmaf(iv1, tv1, VAB1);
        ri0[i] = iv0; ri1[i] = iv1; rt0[i] = tv0; rt1[i] = tv1;
        cI = nI; cT = nT;
    }
    EMIT();   // output row y0

    // ---- steady: 31 more output rows = 3 full ring cycles + 4 tail ----
    #pragma unroll 1
    for (int j = 0; j < 3; j++) {
        #pragma unroll
        for (int k = 0; k < 9; k++) {
            STEADY(k, y0 + 5 + j * 9 + k);
        }
    }
    #pragma unroll
    for (int k = 0; k < 4; k++) {
        STEADY(k, y0 + 32 + k);
    }
    #undef LOADROW
    #undef EMIT
    #undef STEADY

    // ---- reduction: warp -> block -> global partials -> last block finishes ----
    #pragma unroll
    for (int off = 16; off > 0; off >>= 1)
        acc += __shfl_down_sync(0xffffffffu, acc, off);

    __shared__ float sred[WPB];
    __shared__ int   slast;
    if (lane == 0) sred[wid] = acc;
    __syncthreads();
    if (threadIdx.x == 0) {
        g_part[blockIdx.x] = sred[0] + sred[1];
        __threadfence();
        int old = atomicAdd(&g_cnt, 1);
        slast = (old == NBLOCKS - 1) ? 1 : 0;
    }
    __syncthreads();

    if (slast) {
        // 2560 partials = 640 float4; 64 threads -> 10 float4 each
        double d = 0.0;
        const float4* p4 = (const float4*)g_part;
        #pragma unroll
        for (int r = 0; r < 10; r++) {
            const float4 v = p4[threadIdx.x + r * 64];
            d += (double)v.x + (double)v.y + (double)v.z + (double)v.w;
        }
        #pragma unroll
        for (int off = 16; off > 0; off >>= 1)
            d += __shfl_down_sync(0xffffffffu, d, off);
        __shared__ double dred[WPB];
        if (lane == 0) dred[wid] = d;
        __syncthreads();
        if (threadIdx.x == 0) {
            out[0] = (float)(-(dred[0] + dred[1]) / 8388608.0);   // 32*512*512
            g_cnt = 0;                            // reset for next graph replay
        }
    }
}

extern "C" void kernel_launch(void* const* d_in, const int* in_sizes, int n_in,
                              void* d_out, int out_size) {
    const float* inp = (const float*)d_in[0];
    const float* tgt = (const float*)d_in[1];
    // d_in[2] is the all-ones 9x9 filter; baked into the box sums.
    float* out = (float*)d_out;
    cc_kernel<<<NBLOCKS, 64>>>(inp, tgt, out);
}

// round 11
// speedup vs baseline: 1.5484x; 1.0934x over previous
#include <cuda_runtime.h>

#define H 512
#define W 512
#define NB 32
#define OUTW 56            // output columns per warp (lanes 0..27 x 2)
#define STRIPS 10          // 10*56 = 560 >= 512
#define YSEGS 16
#define YLEN 32
#define WARPS_TOTAL (STRIPS * NB * YSEGS)   // 5120
#define WPB 2
#define NBLOCKS (WARPS_TOTAL / WPB)         // 2560
#define RP 256             // float2 row pitch

__device__ float g_part[NBLOCKS];
__device__ int   g_cnt = 0;

// Pair-channel horizontal 9-window sums. Lane l holds columns 2l (a0), 2l+1 (a1).
#define HSUM9P(a0, a1, hE, hO) do {                          \
    float _p  = (a0) + (a1);                                 \
    float _s  = _p + __shfl_down_sync(0xffffffffu, _p, 1);   \
    float _S4 = _s + __shfl_down_sync(0xffffffffu, _s, 2);   \
    (hE) = _S4  + __shfl_down_sync(0xffffffffu, (a0), 4);    \
    (hO) = (a1) + __shfl_down_sync(0xffffffffu, _S4, 1);     \
} while (0)

__global__ __launch_bounds__(64, 12) void cc_kernel(const float* __restrict__ inp,
                                                    const float* __restrict__ tgt,
                                                    float* __restrict__ out) {
    const int lane = threadIdx.x & 31;
    const int wid  = threadIdx.x >> 5;
    const int w    = blockIdx.x * WPB + wid;

    const int strip = w % STRIPS;
    const int rem   = w / STRIPS;          // 0..511
    const int b     = rem >> 4;            // 0..31
    const int y0    = (rem & 15) << 5;     // 0..480

    const int xs  = strip * OUTW;
    const int gx  = xs - 4 + 2 * lane;
    const bool cok = (unsigned)gx < W;
    const bool val = (lane < 28) && ((xs + 2 * lane) < W);   // valE == valO here

    const size_t boff = (size_t)b * (H * W) + (cok ? gx : 0);
    const float2* __restrict__ pI2 = (const float2*)(inp + boff);
    const float2* __restrict__ pT2 = (const float2*)(tgt + boff);

    // vertical ring buffers of RAW rows: 4 values x 9 rows = 36 regs
    float ri0[9], ri1[9], rt0[9], rt1[9];
    #pragma unroll
    for (int k = 0; k < 9; k++) { ri0[k]=0.f; ri1[k]=0.f; rt0[k]=0.f; rt1[k]=0.f; }

    float VA0=0.f, VA1=0.f, VB0=0.f, VB1=0.f, VAA0=0.f, VAA1=0.f,
          VBB0=0.f, VBB1=0.f, VAB0=0.f, VAB1=0.f, acc=0.f;
    const float inv81 = 1.0f / 81.0f;

    #define LOADROW(G, I2v, T2v) do {                              \
        I2v = make_float2(0.f, 0.f);                               \
        T2v = make_float2(0.f, 0.f);                               \
        if (cok && (unsigned)(G) < H) {                            \
            I2v = __ldg(pI2 + (ptrdiff_t)(G) * RP);                \
            const float2 _t = __ldg(pT2 + (ptrdiff_t)(G) * RP);    \
            T2v.x = fmaf(_t.x, 0.5f, 0.5f);                        \
            T2v.y = fmaf(_t.y, 0.5f, 0.5f);                        \
        }                                                          \
    } while (0)

    // sequential-channel emit: minimizes simultaneously-live S values; one
    // fused reciprocal serves both column outputs.
    #define EMIT() do {                                                         \
        float SAE, SAO, SBE, SBO, SXE, SXO;                                     \
        HSUM9P(VA0, VA1, SAE, SAO);                                             \
        HSUM9P(VB0, VB1, SBE, SBO);                                             \
        const float tAE = SAE * inv81, tAO = SAO * inv81;                       \
        const float tBE = SBE * inv81, tBO = SBO * inv81;                       \
        HSUM9P(VAB0, VAB1, SXE, SXO);                                           \
        const float crE = fmaf(-tAE, SBE, SXE);                                 \
        const float crO = fmaf(-tAO, SBO, SXO);                                 \
        HSUM9P(VAA0, VAA1, SXE, SXO);                                           \
        const float ivE = fmaf(-tAE, SAE, SXE);                                 \
        const float ivO = fmaf(-tAO, SAO, SXO);                                 \
        HSUM9P(VBB0, VBB1, SXE, SXO);                                           \
        const float tvE = fmaf(-tBE, SBE, SXE);                                 \
        const float tvO = fmaf(-tBO, SBO, SXO);                                 \
        const float dE  = fmaf(tvE, ivE, 1e-5f);                                \
        const float dO  = fmaf(tvO, ivO, 1e-5f);                                \
        const float nE  = crE * crE;                                            \
        const float nO  = crO * crO;                                            \
        acc += __fdividef(fmaf(nE, dO, nO * dE), dE * dO);                      \
    } while (0)

    #define STEADY(kslot, G) do {                                               \
        float2 nI, nT;                                                          \
        LOADROW((G) + 1, nI, nT);     /* prefetch next enter row */             \
        const float iv0 = cI.x, iv1 = cI.y, tv0 = cT.x, tv1 = cT.y;             \
        const float oi0 = ri0[kslot], oi1 = ri1[kslot];                         \
        const float ot0 = rt0[kslot], ot1 = rt1[kslot];                         \
        VA0 += iv0 - oi0;  VA1 += iv1 - oi1;                                    \
        VB0 += tv0 - ot0;  VB1 += tv1 - ot1;                                    \
        VAA0 = fmaf(-oi0, oi0, fmaf(iv0, iv0, VAA0));                           \
        VAA1 = fmaf(-oi1, oi1, fmaf(iv1, iv1, VAA1));                           \
        VBB0 = fmaf(-ot0, ot0, fmaf(tv0, tv0, VBB0));                           \
        VBB1 = fmaf(-ot1, ot1, fmaf(tv1, tv1, VBB1));                           \
        VAB0 = fmaf(-oi0, ot0, fmaf(iv0, tv0, VAB0));                           \
        VAB1 = fmaf(-oi1, ot1, fmaf(iv1, tv1, VAB1));                           \
        ri0[kslot] = iv0; ri1[kslot] = iv1; rt0[kslot] = tv0; rt1[kslot] = tv1; \
        cI = nI; cT = nT;                                                       \
        EMIT();                                                                 \
    } while (0)

    // prefetch first row (gy = y0-4)
    float2 cI, cT;
    LOADROW(y0 - 4, cI, cT);

    // ---- warmup: rows y0-4 .. y0+4 (slots 0..8), add-only; first output at end ----
    #pragma unroll
    for (int i = 0; i < 9; i++) {
        float2 nI, nT;
        LOADROW(y0 - 3 + i, nI, nT);
        const float iv0 = cI.x, iv1 = cI.y, tv0 = cT.x, tv1 = cT.y;
        VA0 += iv0;  VA1 += iv1;  VB0 += tv0;  VB1 += tv1;
        VAA0 = fmaf(iv0, iv0, VAA0);  VAA1 = fmaf(iv1, iv1, VAA1);
        VBB0 = fmaf(tv0, tv0, VBB0);  VBB1 = fmaf(tv1, tv1, VBB1);
        VAB0 = fmaf(iv0, tv0, VAB0);  VAB1 = fmaf(iv1, tv1, VAB1);
        ri0[i] = iv0; ri1[i] = iv1; rt0[i] = tv0; rt1[i] = tv1;
        cI = nI; cT = nT;
    }
    EMIT();   // output row y0

    // ---- steady: 31 more output rows = 3 full ring cycles + 4 tail ----
    #pragma unroll 1
    for (int j = 0; j < 3; j++) {
        #pragma unroll
        for (int k = 0; k < 9; k++) {
            STEADY(k, y0 + 5 + j * 9 + k);
        }
    }
    #pragma unroll
    for (int k = 0; k < 4; k++) {
        STEADY(k, y0 + 32 + k);
    }
    #undef LOADROW
    #undef EMIT
    #undef STEADY

    // mask invalid lanes once (their garbage is finite; see theory note)
    acc = val ? acc : 0.f;

    // ---- reduction: warp -> block -> global partials -> last block finishes ----
    #pragma unroll
    for (int off = 16; off > 0; off >>= 1)
        acc += __shfl_down_sync(0xffffffffu, acc, off);

    __shared__ float sred[WPB];
    __shared__ int   slast;
    if (lane == 0) sred[wid] = acc;
    __syncthreads();
    if (threadIdx.x == 0) {
        g_part[blockIdx.x] = sred[0] + sred[1];
        __threadfence();
        int old = atomicAdd(&g_cnt, 1);
        slast = (old == NBLOCKS - 1) ? 1 : 0;
    }
    __syncthreads();

    if (slast) {
        // 2560 partials = 640 float4; 64 threads -> 10 float4 each
        double d = 0.0;
        const float4* p4 = (const float4*)g_part;
        #pragma unroll
        for (int r = 0; r < 10; r++) {
            const float4 v = p4[threadIdx.x + r * 64];
            d += (double)v.x + (double)v.y + (double)v.z + (double)v.w;
        }
        #pragma unroll
        for (int off = 16; off > 0; off >>= 1)
            d += __shfl_down_sync(0xffffffffu, d, off);
        __shared__ double dred[WPB];
        if (lane == 0) dred[wid] = d;
        __syncthreads();
        if (threadIdx.x == 0) {
            out[0] = (float)(-(dred[0] + dred[1]) / 8388608.0);   // 32*512*512
            g_cnt = 0;                            // reset for next graph replay
        }
    }
}

extern "C" void kernel_launch(void* const* d_in, const int* in_sizes, int n_in,
                              void* d_out, int out_size) {
    const float* inp = (const float*)d_in[0];
    const float* tgt = (const float*)d_in[1];
    // d_in[2] is the all-ones 9x9 filter; baked into the box sums.
    float* out = (float*)d_out;
    cc_kernel<<<NBLOCKS, 64>>>(inp, tgt, out);
}